// round 14
// baseline (speedup 1.0000x reference)
#include <cuda_runtime.h>
#include <cuda_fp16.h>
#include <cstdint>

// ---------------------------------------------------------------------------
// BitLinear: out = x @ ternary(w)^T + bias
// x: [8192,4096] f32, w: [4096,4096] f32, bias: [4096] f32, out f32.
//
// Cycle model (R12/R13 profiles): MMA floor 2048 cyc/kt/SMSP, wall 2557;
// gap = crossbar interference + 64 barriers/tile straggle. This round:
// BK=128 with 2 stages (same 192KB SMEM, same bytes) -> 32 barriers/tile.
// Pipeline: wait_group(0) -> sync -> load(kt+1) -> commit -> compute(kt).
// kk-stagger reverted (measured neutral-negative).
// ---------------------------------------------------------------------------

#define MDIM 8192
#define NDIM 4096
#define KDIM 4096

#define BM 256
#define BN 128
#define BK 128
#define KT (KDIM / BK)   // 32

// Scratch (device globals: allocation-free per harness rules)
__device__ double   g_partials[512];
__device__ unsigned g_count = 0;
__device__ unsigned g_flag  = 0;
__device__ float    g_gamma_inv;
__device__ __align__(128) __half g_xq[(size_t)MDIM * KDIM];   // 64 MB
__device__ __align__(128) __half g_wq[(size_t)NDIM * KDIM];   // 32 MB

// ---------------------------------------------------------------------------
// Helpers
// ---------------------------------------------------------------------------
static __device__ __forceinline__ uint32_t smem_u32(const void* p) {
    uint32_t a;
    asm("{ .reg .u64 t; cvta.to.shared.u64 t, %1; cvt.u32.u64 %0, t; }"
        : "=r"(a) : "l"(p));
    return a;
}

static __device__ __forceinline__ void cp_async16(uint32_t s, const void* g) {
    asm volatile("cp.async.cg.shared.global [%0], [%1], 16;" :: "r"(s), "l"(g));
}

// SW128-style xor swizzle on byte offsets within 128B rows
#define SWZ(o) ((o) ^ (((o) >> 3) & 0x70))

#define LDSM_X4(r0, r1, r2, r3, addr)                                          \
    asm volatile("ldmatrix.sync.aligned.m8n8.x4.shared.b16 {%0,%1,%2,%3}, [%4];"\
                 : "=r"(r0), "=r"(r1), "=r"(r2), "=r"(r3) : "r"(addr))

#define MMA_16816(c, a, b)                                                     \
    asm volatile(                                                              \
        "mma.sync.aligned.m16n8k16.row.col.f32.f16.f16.f32 "                   \
        "{%0,%1,%2,%3}, {%4,%5,%6,%7}, {%8,%9}, {%0,%1,%2,%3};"                \
        : "+f"((c)[0]), "+f"((c)[1]), "+f"((c)[2]), "+f"((c)[3])               \
        : "r"((a)[0]), "r"((a)[1]), "r"((a)[2]), "r"((a)[3]),                  \
          "r"((b)[0]), "r"((b)[1]))

// ---------------------------------------------------------------------------
// Launch 1: fused prepass (resident-safe single kernel), unchanged from R12.
// ---------------------------------------------------------------------------
#define PRE_GRID 512

__global__ __launch_bounds__(256, 4)
void prepass_fused_kernel(const float* __restrict__ w, const float* __restrict__ x) {
    __shared__ double sred[256];
    __shared__ bool is_last;
    const int tid = threadIdx.x;
    const int gtid = blockIdx.x * 256 + tid;
    const int gstride = PRE_GRID * 256;      // 131072

    // ---- Phase 1: |w| partial sums (32 float4 per thread, exact) ----
    {
        const float4* w4 = reinterpret_cast<const float4*>(w);
        float s0 = 0.f, s1 = 0.f, s2 = 0.f, s3 = 0.f;
        #pragma unroll
        for (int it = 0; it < 8; it++) {
            const int base = gtid + it * 4 * gstride;
            float4 a = w4[base];
            float4 b = w4[base + gstride];
            float4 c = w4[base + 2 * gstride];
            float4 d = w4[base + 3 * gstride];
            s0 += fabsf(a.x) + fabsf(a.y) + fabsf(a.z) + fabsf(a.w);
            s1 += fabsf(b.x) + fabsf(b.y) + fabsf(b.z) + fabsf(b.w);
            s2 += fabsf(c.x) + fabsf(c.y) + fabsf(c.z) + fabsf(c.w);
            s3 += fabsf(d.x) + fabsf(d.y) + fabsf(d.z) + fabsf(d.w);
        }
        sred[tid] = (double)((s0 + s1) + (s2 + s3));
    }
    __syncthreads();
    for (int o = 128; o > 0; o >>= 1) {
        if (tid < o) sred[tid] += sred[tid + o];
        __syncthreads();
    }
    if (tid == 0) {
        g_partials[blockIdx.x] = sred[0];
        __threadfence();
        unsigned c = atomicAdd(&g_count, 1u);
        is_last = (c == PRE_GRID - 1);
    }
    __syncthreads();
    if (is_last) {
        double t = 0.0;
        for (int i = tid; i < PRE_GRID; i += 256) t += __ldcg(&g_partials[i]);
        sred[tid] = t;
        __syncthreads();
        for (int o = 128; o > 0; o >>= 1) {
            if (tid < o) sred[tid] += sred[tid + o];
            __syncthreads();
        }
        if (tid == 0) {
            double g = sred[0] / (double)((size_t)NDIM * KDIM);
            if (g < 1e-8) g = 1e-8;
            g_gamma_inv = (float)(1.0 / g);
            g_count = 0;   // reset for next graph replay
            unsigned one = 1u;
            asm volatile("st.global.release.gpu.u32 [%0], %1;"
                         :: "l"(&g_flag), "r"(one) : "memory");
        }
    }

    // ---- Phase 2: x -> fp16 (gamma-independent; hides reduction latency) ----
    {
        const float4* x4 = reinterpret_cast<const float4*>(x);
        uint2* q = reinterpret_cast<uint2*>(g_xq);
        const int n4 = (MDIM * KDIM) / 4;    // 64 per thread
        #pragma unroll 4
        for (int i = gtid; i < n4; i += gstride) {
            float4 v = x4[i];
            __half2 h0 = __floats2half2_rn(v.x, v.y);
            __half2 h1 = __floats2half2_rn(v.z, v.w);
            uint2 u;
            u.x = *reinterpret_cast<unsigned*>(&h0);
            u.y = *reinterpret_cast<unsigned*>(&h1);
            q[i] = u;
        }
    }

    // ---- Phase 3: wait for gamma (normally already set), then w-quant ----
    {
        unsigned f;
        do {
            asm volatile("ld.global.acquire.gpu.u32 %0, [%1];"
                         : "=r"(f) : "l"(&g_flag));
        } while (f == 0);
        const float ginv = __ldcg(&g_gamma_inv);

        const float4* w4 = reinterpret_cast<const float4*>(w);
        uint2* q = reinterpret_cast<uint2*>(g_wq);
        const int n4 = (NDIM * KDIM) / 4;    // 32 per thread
        #pragma unroll 4
        for (int i = gtid; i < n4; i += gstride) {
            float4 v = w4[i];
            float a = fminf(1.f, fmaxf(-1.f, rintf(v.x * ginv)));
            float b = fminf(1.f, fmaxf(-1.f, rintf(v.y * ginv)));
            float c = fminf(1.f, fmaxf(-1.f, rintf(v.z * ginv)));
            float d = fminf(1.f, fmaxf(-1.f, rintf(v.w * ginv)));
            __half2 h0 = __floats2half2_rn(a, b);
            __half2 h1 = __floats2half2_rn(c, d);
            uint2 u;
            u.x = *reinterpret_cast<unsigned*>(&h0);
            u.y = *reinterpret_cast<unsigned*>(&h1);
            q[i] = u;
        }
    }
}

// ---------------------------------------------------------------------------
// Launch 2: GEMM. 256(M) x 128(N) CTA tile, BK=128, 2-stage cp.async,
// 512 threads (16 warps: wm 0..7 -> 32 rows, wn 0..1 -> 64 cols).
// SMEM rows are stored as 2 x 128B sub-rows per logical 256B row
// (sub-row index sr = row*2 + khalf), SW128 swizzle within each 128B.
// One barrier per kt (32 per tile, halved vs BK=64).
// Pipeline per kt: wait_group(0) -> sync -> load(kt+1) -> commit -> compute.
// ---------------------------------------------------------------------------
static constexpr int A_STAGE = BM * BK * 2;                   // 65536
static constexpr int B_STAGE = BN * BK * 2;                   // 32768
static constexpr int STAGE_BYTES = A_STAGE + B_STAGE;         // 98304
static constexpr int SMEM_BYTES  = 2 * STAGE_BYTES;           // 196608

__global__ __launch_bounds__(512, 1)
void bitlinear_gemm_kernel(const float* __restrict__ bias, float* __restrict__ out) {
    extern __shared__ __align__(128) char smem_raw[];
    const uint32_t sbase = smem_u32(smem_raw);

    const int tid  = threadIdx.x;
    const int wid  = tid >> 5;
    const int lane = tid & 31;
    const int wm = wid & 7;        // 0..7 -> 32 rows each
    const int wn = wid >> 3;       // 0..1 -> 64 cols each
    const int m0 = blockIdx.y * BM;
    const int n0 = blockIdx.x * BN;

    if (tid == 0 && blockIdx.x == 0 && blockIdx.y == 0) g_flag = 0;

    const __half* Ag = g_xq + (size_t)m0 * KDIM;
    const __half* Bg = g_wq + (size_t)n0 * KDIM;

    // Load mapping: chunks of 16B. A: 4096 chunks (512 sub-rows x 8),
    // B: 2048 chunks (256 sub-rows x 8). Thread: kc = tid&7, srb = tid>>3.
    const int srb = tid >> 3;      // 0..63
    const int lkc = tid & 7;

    float acc[2][8][4];
    #pragma unroll
    for (int i = 0; i < 2; i++)
        #pragma unroll
        for (int j = 0; j < 8; j++)
            #pragma unroll
            for (int r = 0; r < 4; r++) acc[i][j][r] = 0.f;

    auto load_stage = [&](int kt) {
        const int s = kt & 1;
        const uint32_t sA = sbase + s * STAGE_BYTES;
        const uint32_t sB = sA + A_STAGE;
        const __half* Akt = Ag + kt * BK;
        const __half* Bkt = Bg + kt * BK;
        #pragma unroll
        for (int i = 0; i < 8; i++) {
            const int sr = srb + i * 64;          // 0..511
            const int r  = sr >> 1;
            const int h  = sr & 1;
            const uint32_t d = SWZ((uint32_t)(sr * 128 + lkc * 16));
            cp_async16(sA + d, Akt + (size_t)r * KDIM + h * 64 + lkc * 8);
        }
        #pragma unroll
        for (int i = 0; i < 4; i++) {
            const int sr = srb + i * 64;          // 0..255
            const int r  = sr >> 1;
            const int h  = sr & 1;
            const uint32_t d = SWZ((uint32_t)(sr * 128 + lkc * 16));
            cp_async16(sB + d, Bkt + (size_t)r * KDIM + h * 64 + lkc * 8);
        }
    };

    // Prologue: stage 0
    load_stage(0);
    asm volatile("cp.async.commit_group;" ::: "memory");

    // ldmatrix lane addressing
    const int a_r  = lane & 15;                          // row within m16
    const int a_ck = (lane >> 4) * 16;                   // k-byte half (16B)
    const int b_n  = ((lane >> 4) & 1) * 8 + (lane & 7); // n row within n16 pair
    const int b_ck = ((lane >> 3) & 1) * 16;             // k-byte half

    for (int kt = 0; kt < KT; ++kt) {
        asm volatile("cp.async.wait_group 0;" ::: "memory");
        __syncthreads();   // all data of stage kt&1 visible to all warps; also
                           // releases stage (kt+1)&1 (finished in iter kt-1)

        if (kt + 1 < KT) load_stage(kt + 1);
        asm volatile("cp.async.commit_group;" ::: "memory");

        const int s = kt & 1;
        const uint32_t sA = sbase + s * STAGE_BYTES;
        const uint32_t sB = sA + A_STAGE;

        #pragma unroll
        for (int kk = 0; kk < 8; kk++) {
            const int ksub = kk >> 2;        // which 128B sub-row half
            const int kln  = (kk & 3) * 32;  // 32B chunk within sub-row
            uint32_t a[2][4];
            #pragma unroll
            for (int i = 0; i < 2; i++) {
                const uint32_t off = (uint32_t)(((wm * 32 + i * 16 + a_r) * 2
                                                 + ksub) * 128 + kln + a_ck);
                LDSM_X4(a[i][0], a[i][1], a[i][2], a[i][3], sA + SWZ(off));
            }
            uint32_t b[8][2];
            #pragma unroll
            for (int jp = 0; jp < 4; jp++) {
                const uint32_t off = (uint32_t)(((wn * 64 + jp * 16 + b_n) * 2
                                                 + ksub) * 128 + kln + b_ck);
                uint32_t r0, r1, r2, r3;
                LDSM_X4(r0, r1, r2, r3, sB + SWZ(off));
                b[jp * 2][0] = r0;     b[jp * 2][1] = r1;
                b[jp * 2 + 1][0] = r2; b[jp * 2 + 1][1] = r3;
            }
            #pragma unroll
            for (int i = 0; i < 2; i++)
                #pragma unroll
                for (int j = 0; j < 8; j++)
                    MMA_16816(acc[i][j], a[i], b[j]);
        }
        // no trailing barrier: next iteration's leading barrier releases
        // this stage before it is overwritten (2-stage ping-pong).
    }

    // Epilogue
    const int er = lane >> 2;
    const int ec = (lane & 3) * 2;
    float bb[8][2];
    #pragma unroll
    for (int j = 0; j < 8; j++) {
        const int col = n0 + wn * 64 + j * 8 + ec;
        bb[j][0] = __ldg(bias + col);
        bb[j][1] = __ldg(bias + col + 1);
    }
    #pragma unroll
    for (int i = 0; i < 2; i++) {
        const int row = m0 + wm * 32 + i * 16 + er;
        #pragma unroll
        for (int j = 0; j < 8; j++) {
            const int col = n0 + wn * 64 + j * 8 + ec;
            float2 v0 = make_float2(acc[i][j][0] + bb[j][0],
                                    acc[i][j][1] + bb[j][1]);
            float2 v1 = make_float2(acc[i][j][2] + bb[j][0],
                                    acc[i][j][3] + bb[j][1]);
            *reinterpret_cast<float2*>(out + (size_t)row * NDIM + col)       = v0;
            *reinterpret_cast<float2*>(out + (size_t)(row + 8) * NDIM + col) = v1;
        }
    }
}

// ---------------------------------------------------------------------------
// Launch
// ---------------------------------------------------------------------------
extern "C" void kernel_launch(void* const* d_in, const int* in_sizes, int n_in,
                              void* d_out, int out_size) {
    const float* x    = (const float*)d_in[0];   // [4,2048,4096]
    const float* w    = (const float*)d_in[1];   // [4096,4096]
    const float* bias = (const float*)d_in[2];   // [4096]
    float* out = (float*)d_out;                  // [4,2048,4096]

    prepass_fused_kernel<<<PRE_GRID, 256>>>(w, x);

    cudaFuncSetAttribute(bitlinear_gemm_kernel,
                         cudaFuncAttributeMaxDynamicSharedMemorySize, SMEM_BYTES);
    bitlinear_gemm_kernel<<<dim3(NDIM / BN, MDIM / BM), 512, SMEM_BYTES>>>(bias, out);
}

// round 16
// speedup vs baseline: 1.4374x; 1.4374x over previous
#include <cuda_runtime.h>
#include <cuda_fp16.h>
#include <cstdint>

// ---------------------------------------------------------------------------
// BitLinear: out = x @ ternary(w)^T + bias
// x: [8192,4096] f32, w: [4096,4096] f32, bias: [4096] f32, out f32.
//
// R14 post-mortem: BK=128 layout doubled LDS cycles (2-way ldmatrix bank
// conflict from even/odd sub-row addressing) -> regression unrelated to the
// barrier hypothesis. This round: R12's proven layout byte-for-byte (BK=64,
// 4 x 48KB stages, SW128), but the mainloop processes kt in PAIRS with one
// wait_group(0) + one __syncthreads per pair -> 32 barriers/tile (was 64).
// Pair p computes buffers {2(p&1), 2(p&1)+1}; pair p+1 loads the other half,
// released by this pair's barrier. Prefetch hidden under a full pair compute.
// ---------------------------------------------------------------------------

#define MDIM 8192
#define NDIM 4096
#define KDIM 4096

#define BM 256
#define BN 128
#define BK 64
#define KT (KDIM / BK)     // 64
#define NPAIRS (KT / 2)    // 32

// Scratch (device globals: allocation-free per harness rules)
__device__ double   g_partials[512];
__device__ unsigned g_count = 0;
__device__ unsigned g_flag  = 0;
__device__ float    g_gamma_inv;
__device__ __align__(128) __half g_xq[(size_t)MDIM * KDIM];   // 64 MB
__device__ __align__(128) __half g_wq[(size_t)NDIM * KDIM];   // 32 MB

// ---------------------------------------------------------------------------
// Helpers
// ---------------------------------------------------------------------------
static __device__ __forceinline__ uint32_t smem_u32(const void* p) {
    uint32_t a;
    asm("{ .reg .u64 t; cvta.to.shared.u64 t, %1; cvt.u32.u64 %0, t; }"
        : "=r"(a) : "l"(p));
    return a;
}

static __device__ __forceinline__ void cp_async16(uint32_t s, const void* g) {
    asm volatile("cp.async.cg.shared.global [%0], [%1], 16;" :: "r"(s), "l"(g));
}

// SW128-style xor swizzle on byte offsets within 128B rows
#define SWZ(o) ((o) ^ (((o) >> 3) & 0x70))

#define LDSM_X4(r0, r1, r2, r3, addr)                                          \
    asm volatile("ldmatrix.sync.aligned.m8n8.x4.shared.b16 {%0,%1,%2,%3}, [%4];"\
                 : "=r"(r0), "=r"(r1), "=r"(r2), "=r"(r3) : "r"(addr))

#define MMA_16816(c, a, b)                                                     \
    asm volatile(                                                              \
        "mma.sync.aligned.m16n8k16.row.col.f32.f16.f16.f32 "                   \
        "{%0,%1,%2,%3}, {%4,%5,%6,%7}, {%8,%9}, {%0,%1,%2,%3};"                \
        : "+f"((c)[0]), "+f"((c)[1]), "+f"((c)[2]), "+f"((c)[3])               \
        : "r"((a)[0]), "r"((a)[1]), "r"((a)[2]), "r"((a)[3]),                  \
          "r"((b)[0]), "r"((b)[1]))

// ---------------------------------------------------------------------------
// Launch 1: fused prepass (resident-safe single kernel), unchanged from R12.
// ---------------------------------------------------------------------------
#define PRE_GRID 512

__global__ __launch_bounds__(256, 4)
void prepass_fused_kernel(const float* __restrict__ w, const float* __restrict__ x) {
    __shared__ double sred[256];
    __shared__ bool is_last;
    const int tid = threadIdx.x;
    const int gtid = blockIdx.x * 256 + tid;
    const int gstride = PRE_GRID * 256;      // 131072

    // ---- Phase 1: |w| partial sums (32 float4 per thread, exact) ----
    {
        const float4* w4 = reinterpret_cast<const float4*>(w);
        float s0 = 0.f, s1 = 0.f, s2 = 0.f, s3 = 0.f;
        #pragma unroll
        for (int it = 0; it < 8; it++) {
            const int base = gtid + it * 4 * gstride;
            float4 a = w4[base];
            float4 b = w4[base + gstride];
            float4 c = w4[base + 2 * gstride];
            float4 d = w4[base + 3 * gstride];
            s0 += fabsf(a.x) + fabsf(a.y) + fabsf(a.z) + fabsf(a.w);
            s1 += fabsf(b.x) + fabsf(b.y) + fabsf(b.z) + fabsf(b.w);
            s2 += fabsf(c.x) + fabsf(c.y) + fabsf(c.z) + fabsf(c.w);
            s3 += fabsf(d.x) + fabsf(d.y) + fabsf(d.z) + fabsf(d.w);
        }
        sred[tid] = (double)((s0 + s1) + (s2 + s3));
    }
    __syncthreads();
    for (int o = 128; o > 0; o >>= 1) {
        if (tid < o) sred[tid] += sred[tid + o];
        __syncthreads();
    }
    if (tid == 0) {
        g_partials[blockIdx.x] = sred[0];
        __threadfence();
        unsigned c = atomicAdd(&g_count, 1u);
        is_last = (c == PRE_GRID - 1);
    }
    __syncthreads();
    if (is_last) {
        double t = 0.0;
        for (int i = tid; i < PRE_GRID; i += 256) t += __ldcg(&g_partials[i]);
        sred[tid] = t;
        __syncthreads();
        for (int o = 128; o > 0; o >>= 1) {
            if (tid < o) sred[tid] += sred[tid + o];
            __syncthreads();
        }
        if (tid == 0) {
            double g = sred[0] / (double)((size_t)NDIM * KDIM);
            if (g < 1e-8) g = 1e-8;
            g_gamma_inv = (float)(1.0 / g);
            g_count = 0;   // reset for next graph replay
            unsigned one = 1u;
            asm volatile("st.global.release.gpu.u32 [%0], %1;"
                         :: "l"(&g_flag), "r"(one) : "memory");
        }
    }

    // ---- Phase 2: x -> fp16 (gamma-independent; hides reduction latency) ----
    {
        const float4* x4 = reinterpret_cast<const float4*>(x);
        uint2* q = reinterpret_cast<uint2*>(g_xq);
        const int n4 = (MDIM * KDIM) / 4;    // 64 per thread
        #pragma unroll 4
        for (int i = gtid; i < n4; i += gstride) {
            float4 v = x4[i];
            __half2 h0 = __floats2half2_rn(v.x, v.y);
            __half2 h1 = __floats2half2_rn(v.z, v.w);
            uint2 u;
            u.x = *reinterpret_cast<unsigned*>(&h0);
            u.y = *reinterpret_cast<unsigned*>(&h1);
            q[i] = u;
        }
    }

    // ---- Phase 3: wait for gamma (normally already set), then w-quant ----
    {
        unsigned f;
        do {
            asm volatile("ld.global.acquire.gpu.u32 %0, [%1];"
                         : "=r"(f) : "l"(&g_flag));
        } while (f == 0);
        const float ginv = __ldcg(&g_gamma_inv);

        const float4* w4 = reinterpret_cast<const float4*>(w);
        uint2* q = reinterpret_cast<uint2*>(g_wq);
        const int n4 = (NDIM * KDIM) / 4;    // 32 per thread
        #pragma unroll 4
        for (int i = gtid; i < n4; i += gstride) {
            float4 v = w4[i];
            float a = fminf(1.f, fmaxf(-1.f, rintf(v.x * ginv)));
            float b = fminf(1.f, fmaxf(-1.f, rintf(v.y * ginv)));
            float c = fminf(1.f, fmaxf(-1.f, rintf(v.z * ginv)));
            float d = fminf(1.f, fmaxf(-1.f, rintf(v.w * ginv)));
            __half2 h0 = __floats2half2_rn(a, b);
            __half2 h1 = __floats2half2_rn(c, d);
            uint2 u;
            u.x = *reinterpret_cast<unsigned*>(&h0);
            u.y = *reinterpret_cast<unsigned*>(&h1);
            q[i] = u;
        }
    }
}

// ---------------------------------------------------------------------------
// Launch 2: GEMM. 256(M) x 128(N) CTA tile, BK=64, 4 x 48KB stages (R12
// layout byte-identical), 512 threads (16 warps: wm 0..7 -> 32 rows,
// wn 0..1 -> 64 cols). PAIR-GRANULAR pipeline: one wait_group(0) + one
// __syncthreads per 2 kt. Pair p computes buffers {2(p&1), 2(p&1)+1};
// loads pair p+1 into the other half right after the barrier.
// ---------------------------------------------------------------------------
static constexpr int A_STAGE = BM * BK * 2;                   // 32768
static constexpr int B_STAGE = BN * BK * 2;                   // 16384
static constexpr int STAGE_BYTES = A_STAGE + B_STAGE;         // 49152
static constexpr int SMEM_BYTES  = 4 * STAGE_BYTES;           // 196608

__global__ __launch_bounds__(512, 1)
void bitlinear_gemm_kernel(const float* __restrict__ bias, float* __restrict__ out) {
    extern __shared__ __align__(128) char smem_raw[];
    const uint32_t sbase = smem_u32(smem_raw);

    const int tid  = threadIdx.x;
    const int wid  = tid >> 5;
    const int lane = tid & 31;
    const int wm = wid & 7;        // 0..7 -> 32 rows each
    const int wn = wid >> 3;       // 0..1 -> 64 cols each
    const int m0 = blockIdx.y * BM;
    const int n0 = blockIdx.x * BN;

    if (tid == 0 && blockIdx.x == 0 && blockIdx.y == 0) g_flag = 0;

    const __half* Ag = g_xq + (size_t)m0 * KDIM;
    const __half* Bg = g_wq + (size_t)n0 * KDIM;

    const int lrow = tid >> 3;     // 0..63
    const int lkc  = tid & 7;

    float acc[2][8][4];
    #pragma unroll
    for (int i = 0; i < 2; i++)
        #pragma unroll
        for (int j = 0; j < 8; j++)
            #pragma unroll
            for (int r = 0; r < 4; r++) acc[i][j][r] = 0.f;

    // Load one BK=64 stage (kt) into buffer s (R12 addressing, unchanged).
    auto load_stage = [&](int kt, int s) {
        const uint32_t sA = sbase + s * STAGE_BYTES;
        const uint32_t sB = sA + A_STAGE;
        const __half* Akt = Ag + kt * BK;
        const __half* Bkt = Bg + kt * BK;
        #pragma unroll
        for (int i = 0; i < 4; i++) {
            const int r = lrow + i * 64;
            const uint32_t d = SWZ((uint32_t)(r * 128 + lkc * 16));
            cp_async16(sA + d, Akt + (size_t)r * KDIM + lkc * 8);
        }
        #pragma unroll
        for (int i = 0; i < 2; i++) {
            const int r = lrow + i * 64;
            const uint32_t d = SWZ((uint32_t)(r * 128 + lkc * 16));
            cp_async16(sB + d, Bkt + (size_t)r * KDIM + lkc * 8);
        }
    };

    // Prologue: pair 0 -> buffers {0,1}, one group.
    load_stage(0, 0);
    load_stage(1, 1);
    asm volatile("cp.async.commit_group;" ::: "memory");

    // ldmatrix lane addressing
    const int a_r  = lane & 15;                          // row within m16
    const int a_ck = (lane >> 4) * 16;                   // k-byte half
    const int b_n  = ((lane >> 4) & 1) * 8 + (lane & 7); // n row within n16 pair
    const int b_ck = ((lane >> 3) & 1) * 16;             // k-byte half

    for (int p = 0; p < NPAIRS; ++p) {
        // Pair p's group is the only outstanding one.
        asm volatile("cp.async.wait_group 0;" ::: "memory");
        __syncthreads();   // pair p data visible; half used by pair p-1 freed

        // Prefetch pair p+1 into the freed half.
        if (p + 1 < NPAIRS) {
            const int b0 = 2 * ((p + 1) & 1);
            load_stage(2 * (p + 1),     b0);
            load_stage(2 * (p + 1) + 1, b0 + 1);
        }
        asm volatile("cp.async.commit_group;" ::: "memory");

        // Compute the two kts of pair p (buffers 2(p&1), 2(p&1)+1).
        #pragma unroll
        for (int q = 0; q < 2; q++) {
            const int s = 2 * (p & 1) + q;
            const uint32_t sA = sbase + s * STAGE_BYTES;
            const uint32_t sB = sA + A_STAGE;

            #pragma unroll
            for (int kk = 0; kk < 4; kk++) {
                uint32_t a[2][4];
                #pragma unroll
                for (int i = 0; i < 2; i++) {
                    const uint32_t off = (uint32_t)((wm * 32 + i * 16 + a_r) * 128
                                                    + kk * 32 + a_ck);
                    LDSM_X4(a[i][0], a[i][1], a[i][2], a[i][3], sA + SWZ(off));
                }
                uint32_t b[8][2];
                #pragma unroll
                for (int jp = 0; jp < 4; jp++) {
                    const uint32_t off = (uint32_t)((wn * 64 + jp * 16 + b_n) * 128
                                                    + kk * 32 + b_ck);
                    uint32_t r0, r1, r2, r3;
                    LDSM_X4(r0, r1, r2, r3, sB + SWZ(off));
                    b[jp * 2][0] = r0;     b[jp * 2][1] = r1;
                    b[jp * 2 + 1][0] = r2; b[jp * 2 + 1][1] = r3;
                }
                #pragma unroll
                for (int i = 0; i < 2; i++)
                    #pragma unroll
                    for (int j = 0; j < 8; j++)
                        MMA_16816(acc[i][j], a[i], b[j]);
            }
        }
        // no trailing barrier: next pair's barrier frees this half before
        // pair p+2's loads touch it.
    }

    // Epilogue
    const int er = lane >> 2;
    const int ec = (lane & 3) * 2;
    float bb[8][2];
    #pragma unroll
    for (int j = 0; j < 8; j++) {
        const int col = n0 + wn * 64 + j * 8 + ec;
        bb[j][0] = __ldg(bias + col);
        bb[j][1] = __ldg(bias + col + 1);
    }
    #pragma unroll
    for (int i = 0; i < 2; i++) {
        const int row = m0 + wm * 32 + i * 16 + er;
        #pragma unroll
        for (int j = 0; j < 8; j++) {
            const int col = n0 + wn * 64 + j * 8 + ec;
            float2 v0 = make_float2(acc[i][j][0] + bb[j][0],
                                    acc[i][j][1] + bb[j][1]);
            float2 v1 = make_float2(acc[i][j][2] + bb[j][0],
                                    acc[i][j][3] + bb[j][1]);
            *reinterpret_cast<float2*>(out + (size_t)row * NDIM + col)       = v0;
            *reinterpret_cast<float2*>(out + (size_t)(row + 8) * NDIM + col) = v1;
        }
    }
}

// ---------------------------------------------------------------------------
// Launch
// ---------------------------------------------------------------------------
extern "C" void kernel_launch(void* const* d_in, const int* in_sizes, int n_in,
                              void* d_out, int out_size) {
    const float* x    = (const float*)d_in[0];   // [4,2048,4096]
    const float* w    = (const float*)d_in[1];   // [4096,4096]
    const float* bias = (const float*)d_in[2];   // [4096]
    float* out = (float*)d_out;                  // [4,2048,4096]

    prepass_fused_kernel<<<PRE_GRID, 256>>>(w, x);

    cudaFuncSetAttribute(bitlinear_gemm_kernel,
                         cudaFuncAttributeMaxDynamicSharedMemorySize, SMEM_BYTES);
    bitlinear_gemm_kernel<<<dim3(NDIM / BN, MDIM / BM), 512, SMEM_BYTES>>>(bias, out);
}